// round 6
// baseline (speedup 1.0000x reference)
#include <cuda_runtime.h>
#include <cuda_fp16.h>
#include <cuda_fp8.h>
#include <cstdint>

#define DEV_INLINE __device__ __forceinline__

// ---------------------------------------------------------------------------
// Scratch (static device globals — allocation-free per harness rules)
// M=16384, K=4096, N=4096.
// ---------------------------------------------------------------------------
static __device__ __half g_A[(size_t)16384 * 4096];  // dequant x, fp16, [M,K]
static __device__ __half g_B[(size_t)4096 * 4096];   // dequant W, fp16, [K,N]

// ---------------------------------------------------------------------------
// Quantize + dequantize. One warp handles TWO 128-elem blocks per iteration
// (independent shfl reduction chains interleave -> hides SHFL latency).
// Exact reference math: scale = max(amax/448, 1e-12); q = fp8_e4m3(v/scale);
// dq = float(q)*scale; one fp16 rounding at the end (only added approx).
// ---------------------------------------------------------------------------
__global__ void quant_kernel(const float* __restrict__ in,
                             __half* __restrict__ out, int npairs) {
    const int pair = (blockIdx.x * blockDim.x + threadIdx.x) >> 5;
    const int lane = threadIdx.x & 31;
    if (pair >= npairs) return;
    const size_t base = (size_t)pair * 256;

    const float4 va = reinterpret_cast<const float4*>(in + base)[lane];
    const float4 vb = reinterpret_cast<const float4*>(in + base + 128)[lane];

    float aa = fmaxf(fmaxf(fabsf(va.x), fabsf(va.y)), fmaxf(fabsf(va.z), fabsf(va.w)));
    float ab = fmaxf(fmaxf(fabsf(vb.x), fabsf(vb.y)), fmaxf(fabsf(vb.z), fabsf(vb.w)));
#pragma unroll
    for (int o = 16; o > 0; o >>= 1) {
        aa = fmaxf(aa, __shfl_xor_sync(0xFFFFFFFFu, aa, o));
        ab = fmaxf(ab, __shfl_xor_sync(0xFFFFFFFFu, ab, o));
    }
    const float sa = fmaxf(__fdiv_rn(aa, 448.0f), 1e-12f);
    const float sb = fmaxf(__fdiv_rn(ab, 448.0f), 1e-12f);

    float fa[4] = {va.x, va.y, va.z, va.w};
    float fb[4] = {vb.x, vb.y, vb.z, vb.w};
    __half ha[4], hb[4];
#pragma unroll
    for (int i = 0; i < 4; i++) {
        __nv_fp8_storage_t qa =
            __nv_cvt_float_to_fp8(__fdiv_rn(fa[i], sa), __NV_SATFINITE, __NV_E4M3);
        __nv_fp8_storage_t qb =
            __nv_cvt_float_to_fp8(__fdiv_rn(fb[i], sb), __NV_SATFINITE, __NV_E4M3);
        __half_raw ra = __nv_cvt_fp8_to_halfraw(qa, __NV_E4M3);
        __half_raw rb = __nv_cvt_fp8_to_halfraw(qb, __NV_E4M3);
        ha[i] = __float2half_rn(__half2float(__half(ra)) * sa);
        hb[i] = __float2half_rn(__half2float(__half(rb)) * sb);
    }
    reinterpret_cast<uint2*>(out + base)[lane] = *reinterpret_cast<const uint2*>(ha);
    reinterpret_cast<uint2*>(out + base + 128)[lane] = *reinterpret_cast<const uint2*>(hb);
}

// ---------------------------------------------------------------------------
// mma.sync GEMM: C[M,N] = A[M,K] @ B[K,N] + bias.
// CTA 128x128x64, 3-stage cp.async, 4 warps (2x2), warp tile 64x64,
// 2 CTAs/SM. Larger warp tile cuts smem crossbar traffic 25% vs 64x32.
// ---------------------------------------------------------------------------
static constexpr int BM = 128, BN = 128, BK = 64, STAGES = 3;
static constexpr int LDA = BK + 8;    // 72 halves = 144B
static constexpr int LDB = BN + 8;    // 136 halves = 272B
static constexpr int A_STAGE = BM * LDA;          // halves
static constexpr int B_STAGE = BK * LDB;          // halves
static constexpr size_t SMEM_BYTES = (size_t)STAGES * (A_STAGE + B_STAGE) * 2;  // 107520

DEV_INLINE uint32_t smem_u32(const void* p) {
    return (uint32_t)__cvta_generic_to_shared(p);
}
DEV_INLINE void cp_async_16(uint32_t dst, const void* src) {
    asm volatile("cp.async.cg.shared.global [%0], [%1], 16;\n" :: "r"(dst), "l"(src));
}
DEV_INLINE void cp_commit() { asm volatile("cp.async.commit_group;\n"); }
template <int NN> DEV_INLINE void cp_wait() {
    asm volatile("cp.async.wait_group %0;\n" :: "n"(NN));
}
DEV_INLINE void ldsm_x4(uint32_t* r, uint32_t addr) {
    asm volatile("ldmatrix.sync.aligned.m8n8.x4.shared.b16 {%0,%1,%2,%3}, [%4];"
                 : "=r"(r[0]), "=r"(r[1]), "=r"(r[2]), "=r"(r[3]) : "r"(addr));
}
DEV_INLINE void ldsm_x4_t(uint32_t* r, uint32_t addr) {
    asm volatile("ldmatrix.sync.aligned.m8n8.x4.trans.shared.b16 {%0,%1,%2,%3}, [%4];"
                 : "=r"(r[0]), "=r"(r[1]), "=r"(r[2]), "=r"(r[3]) : "r"(addr));
}
DEV_INLINE void mma_16816(float* d, const uint32_t* a, const uint32_t* b) {
    asm volatile(
        "mma.sync.aligned.m16n8k16.row.col.f32.f16.f16.f32 "
        "{%0,%1,%2,%3}, {%4,%5,%6,%7}, {%8,%9}, {%0,%1,%2,%3};"
        : "+f"(d[0]), "+f"(d[1]), "+f"(d[2]), "+f"(d[3])
        : "r"(a[0]), "r"(a[1]), "r"(a[2]), "r"(a[3]), "r"(b[0]), "r"(b[1]));
}

__global__ void __launch_bounds__(128, 2)
gemm_mma_kernel(const __half* __restrict__ A, const __half* __restrict__ B,
                const float* __restrict__ bias, float* __restrict__ C,
                int M, int N, int K) {
    extern __shared__ __align__(128) __half smem[];
    __half* sA = smem;                          // [STAGES][BM][LDA]
    __half* sB = smem + STAGES * A_STAGE;       // [STAGES][BK][LDB]

    const int tid = threadIdx.x;
    const int lane = tid & 31;
    const int warp = tid >> 5;                  // 0..3
    const int wm = (warp & 1) * 64;             // 2 warps along M (64 rows)
    const int wn = (warp >> 1) * 64;            // 2 warps along N (64 cols)

    // panel swizzle: 512-CTA panels (16 bm x 32 bn)
    const int linear = blockIdx.y * gridDim.x + blockIdx.x;  // grid=(32,128)
    const int bm = (linear >> 9) * 16 + (linear & 15);
    const int bn = (linear >> 4) & 31;

    const __half* Ab = A + (size_t)bm * BM * K;
    const __half* Bb = B + (size_t)bn * BN;

    const uint32_t sAu = smem_u32(sA);
    const uint32_t sBu = smem_u32(sB);

    // producer (128 threads): A = 1024 x 16B chunks, B = 1024 chunks
    auto issue = [&](int stage, int kt) {
        const int k0 = kt * BK;
        const uint32_t aBase = sAu + stage * A_STAGE * 2;
        const uint32_t bBase = sBu + stage * B_STAGE * 2;
#pragma unroll
        for (int t = 0; t < 8; t++) {
            int c = tid + t * 128;
            int row = c >> 3, ch = c & 7;
            cp_async_16(aBase + (row * LDA + ch * 8) * 2,
                        Ab + (size_t)row * K + k0 + ch * 8);
        }
#pragma unroll
        for (int t = 0; t < 8; t++) {
            int c = tid + t * 128;
            int row = c >> 4, ch = c & 15;
            cp_async_16(bBase + (row * LDB + ch * 8) * 2,
                        Bb + (size_t)(k0 + row) * N + ch * 8);
        }
        cp_commit();
    };

    float acc[4][8][4];
#pragma unroll
    for (int i = 0; i < 4; i++)
#pragma unroll
        for (int j = 0; j < 8; j++)
#pragma unroll
            for (int r = 0; r < 4; r++) acc[i][j][r] = 0.0f;

    const int KT = K / BK;
    issue(0, 0);
    issue(1, 1);

    // ldmatrix lane geometry (validated R4/R5)
    const int q = lane >> 3, r8 = lane & 7;
    const int aRow = r8 + (q & 1) * 8;
    const int aK8 = (q >> 1) * 8;
    const int bRow = r8 + (q & 1) * 8;
    const int bC8 = (q >> 1) * 8;

    for (int kt = 0; kt < KT; kt++) {
        cp_wait<STAGES - 2>();
        __syncthreads();   // also guards reuse of stage (kt-1)%3 prefetch target
        const int s = kt % STAGES;

        if (kt + 2 < KT) issue((kt + 2) % STAGES, kt + 2);
        else cp_commit();                        // uniform group accounting

        const uint32_t aSt = sAu + s * A_STAGE * 2;
        const uint32_t bSt = sBu + s * B_STAGE * 2;
#pragma unroll
        for (int kk = 0; kk < BK / 16; kk++) {
            uint32_t ra[4][4], rb[8][2];
#pragma unroll
            for (int i = 0; i < 4; i++)
                ldsm_x4(ra[i], aSt + ((wm + i * 16 + aRow) * LDA + kk * 16 + aK8) * 2);
#pragma unroll
            for (int p = 0; p < 4; p++) {
                uint32_t t4[4];
                ldsm_x4_t(t4, bSt + ((kk * 16 + bRow) * LDB + wn + p * 16 + bC8) * 2);
                rb[2 * p][0] = t4[0]; rb[2 * p][1] = t4[1];
                rb[2 * p + 1][0] = t4[2]; rb[2 * p + 1][1] = t4[3];
            }
#pragma unroll
            for (int i = 0; i < 4; i++)
#pragma unroll
                for (int j = 0; j < 8; j++)
                    mma_16816(acc[i][j], ra[i], rb[j]);
        }
    }

    // epilogue: fused bias, direct stores
    const int gId = lane >> 2, tI = lane & 3;
#pragma unroll
    for (int i = 0; i < 4; i++) {
        const int row0 = bm * BM + wm + i * 16 + gId;
#pragma unroll
        for (int j = 0; j < 8; j++) {
            const int col = bn * BN + wn + j * 8 + tI * 2;
            const float bx = bias[col], by = bias[col + 1];
            float2 v0 = make_float2(acc[i][j][0] + bx, acc[i][j][1] + by);
            float2 v1 = make_float2(acc[i][j][2] + bx, acc[i][j][3] + by);
            *reinterpret_cast<float2*>(C + (size_t)row0 * N + col) = v0;
            *reinterpret_cast<float2*>(C + (size_t)(row0 + 8) * N + col) = v1;
        }
    }
}

// ---------------------------------------------------------------------------
// Launch
// ---------------------------------------------------------------------------
extern "C" void kernel_launch(void* const* d_in, const int* in_sizes, int n_in,
                              void* d_out, int out_size) {
    const float* x    = (const float*)d_in[0];   // [M, K]
    const float* w    = (const float*)d_in[1];   // [K, N]
    const float* bias = (const float*)d_in[2];   // [N]

    const int N = in_sizes[2];
    const int K = in_sizes[1] / N;
    const int M = in_sizes[0] / K;

    __half* gA = nullptr;
    __half* gB = nullptr;
    cudaGetSymbolAddress((void**)&gA, g_A);
    cudaGetSymbolAddress((void**)&gB, g_B);

    {   // quant+dequant x and W (both have contiguous 128-blocks)
        int pairsA = in_sizes[0] / 256;
        int pairsB = in_sizes[1] / 256;
        quant_kernel<<<(pairsA + 7) / 8, 256>>>(x, gA, pairsA);
        quant_kernel<<<(pairsB + 7) / 8, 256>>>(w, gB, pairsB);
    }
    {   // GEMM + fused bias
        static bool attr_set = false;
        if (!attr_set) {
            cudaFuncSetAttribute(gemm_mma_kernel,
                                 cudaFuncAttributeMaxDynamicSharedMemorySize,
                                 (int)SMEM_BYTES);
            attr_set = true;
        }
        dim3 grid(N / BN, M / BM);   // (32, 128) -> panel swizzle inside
        gemm_mma_kernel<<<grid, 128, SMEM_BYTES>>>(gA, gB, bias, (float*)d_out,
                                                   M, N, K);
    }
}

// round 7
// speedup vs baseline: 1.1284x; 1.1284x over previous
#include <cuda_runtime.h>
#include <cuda_fp16.h>
#include <cuda_fp8.h>
#include <cstdint>

#define DEV_INLINE __device__ __forceinline__

// ---------------------------------------------------------------------------
// Scratch (static device globals — allocation-free per harness rules)
// M=16384, K=4096, N=4096.
// ---------------------------------------------------------------------------
static __device__ __half g_A[(size_t)16384 * 4096];  // dequant x, fp16, [M,K]
static __device__ __half g_B[(size_t)4096 * 4096];   // dequant W, fp16, [K,N]

// ---------------------------------------------------------------------------
// Quantize + dequantize. One warp handles FOUR 128-elem blocks per iteration
// (4 independent load streams + interleaved shfl chains -> high MLP).
// Exact reference math: scale = max(amax/448, 1e-12); q = fp8_e4m3(v/scale);
// dq = float(q)*scale; one fp16 rounding at the end (only added approx).
// ---------------------------------------------------------------------------
__global__ void quant_kernel(const float* __restrict__ in,
                             __half* __restrict__ out, int nquads) {
    const int quad = (blockIdx.x * blockDim.x + threadIdx.x) >> 5;
    const int lane = threadIdx.x & 31;
    if (quad >= nquads) return;
    const size_t base = (size_t)quad * 512;

    float4 v[4];
#pragma unroll
    for (int b = 0; b < 4; b++)
        v[b] = reinterpret_cast<const float4*>(in + base + b * 128)[lane];

    float am[4];
#pragma unroll
    for (int b = 0; b < 4; b++)
        am[b] = fmaxf(fmaxf(fabsf(v[b].x), fabsf(v[b].y)),
                      fmaxf(fabsf(v[b].z), fabsf(v[b].w)));
#pragma unroll
    for (int o = 16; o > 0; o >>= 1) {
#pragma unroll
        for (int b = 0; b < 4; b++)
            am[b] = fmaxf(am[b], __shfl_xor_sync(0xFFFFFFFFu, am[b], o));
    }

#pragma unroll
    for (int b = 0; b < 4; b++) {
        const float s = fmaxf(__fdiv_rn(am[b], 448.0f), 1e-12f);
        float f[4] = {v[b].x, v[b].y, v[b].z, v[b].w};
        __half h[4];
#pragma unroll
        for (int i = 0; i < 4; i++) {
            __nv_fp8_storage_t q =
                __nv_cvt_float_to_fp8(__fdiv_rn(f[i], s), __NV_SATFINITE, __NV_E4M3);
            __half_raw hr = __nv_cvt_fp8_to_halfraw(q, __NV_E4M3);
            h[i] = __float2half_rn(__half2float(__half(hr)) * s);
        }
        reinterpret_cast<uint2*>(out + base + b * 128)[lane] =
            *reinterpret_cast<const uint2*>(h);
    }
}

// ---------------------------------------------------------------------------
// mma.sync GEMM: C[M,N] = A[M,K] @ B[K,N] + bias.
// CTA 128x128x64, 3-stage cp.async, 8 warps (2x4), warp tile 64x32,
// 2 CTAs/SM, single __syncthreads per iter, B-fragment ping-pong prefetch.
// ---------------------------------------------------------------------------
static constexpr int BM = 128, BN = 128, BK = 64, STAGES = 3;
static constexpr int LDA = BK + 8;    // 72 halves = 144B (conflict-free ldsm)
static constexpr int LDB = BN + 8;    // 136 halves = 272B
static constexpr int A_STAGE = BM * LDA;          // halves
static constexpr int B_STAGE = BK * LDB;          // halves
static constexpr size_t SMEM_BYTES = (size_t)STAGES * (A_STAGE + B_STAGE) * 2;  // 107520

DEV_INLINE uint32_t smem_u32(const void* p) {
    return (uint32_t)__cvta_generic_to_shared(p);
}
DEV_INLINE void cp_async_16(uint32_t dst, const void* src) {
    asm volatile("cp.async.cg.shared.global [%0], [%1], 16;\n" :: "r"(dst), "l"(src));
}
DEV_INLINE void cp_commit() { asm volatile("cp.async.commit_group;\n"); }
template <int NN> DEV_INLINE void cp_wait() {
    asm volatile("cp.async.wait_group %0;\n" :: "n"(NN));
}
DEV_INLINE void ldsm_x4(uint32_t* r, uint32_t addr) {
    asm volatile("ldmatrix.sync.aligned.m8n8.x4.shared.b16 {%0,%1,%2,%3}, [%4];"
                 : "=r"(r[0]), "=r"(r[1]), "=r"(r[2]), "=r"(r[3]) : "r"(addr));
}
DEV_INLINE void ldsm_x4_t(uint32_t* r, uint32_t addr) {
    asm volatile("ldmatrix.sync.aligned.m8n8.x4.trans.shared.b16 {%0,%1,%2,%3}, [%4];"
                 : "=r"(r[0]), "=r"(r[1]), "=r"(r[2]), "=r"(r[3]) : "r"(addr));
}
DEV_INLINE void mma_16816(float* d, const uint32_t* a, const uint32_t* b) {
    asm volatile(
        "mma.sync.aligned.m16n8k16.row.col.f32.f16.f16.f32 "
        "{%0,%1,%2,%3}, {%4,%5,%6,%7}, {%8,%9}, {%0,%1,%2,%3};"
        : "+f"(d[0]), "+f"(d[1]), "+f"(d[2]), "+f"(d[3])
        : "r"(a[0]), "r"(a[1]), "r"(a[2]), "r"(a[3]), "r"(b[0]), "r"(b[1]));
}

__global__ void __launch_bounds__(256, 2)
gemm_mma_kernel(const __half* __restrict__ A, const __half* __restrict__ B,
                const float* __restrict__ bias, float* __restrict__ C,
                int M, int N, int K) {
    extern __shared__ __align__(128) __half smem[];
    __half* sA = smem;                          // [STAGES][BM][LDA]
    __half* sB = smem + STAGES * A_STAGE;       // [STAGES][BK][LDB]

    const int tid = threadIdx.x;
    const int lane = tid & 31;
    const int warp = tid >> 5;
    const int wm = (warp & 1) * 64;             // 2 warps along M (64 rows)
    const int wn = (warp >> 1) * 32;            // 4 warps along N (32 cols)

    // panel swizzle: 512-CTA panels (16 bm x 32 bn)
    const int linear = blockIdx.y * gridDim.x + blockIdx.x;  // grid=(32,128)
    const int bm = (linear >> 9) * 16 + (linear & 15);
    const int bn = (linear >> 4) & 31;

    const __half* Ab = A + (size_t)bm * BM * K;
    const __half* Bb = B + (size_t)bn * BN;

    const uint32_t sAu = smem_u32(sA);
    const uint32_t sBu = smem_u32(sB);

    // producer: A = 1024 x 16B chunks (128 rows x 8), B = 1024 (64 rows x 16)
    auto issue = [&](int stage, int kt) {
        const int k0 = kt * BK;
        const uint32_t aBase = sAu + stage * A_STAGE * 2;
        const uint32_t bBase = sBu + stage * B_STAGE * 2;
#pragma unroll
        for (int t = 0; t < 4; t++) {
            int c = tid + t * 256;
            int row = c >> 3, ch = c & 7;
            cp_async_16(aBase + (row * LDA + ch * 8) * 2,
                        Ab + (size_t)row * K + k0 + ch * 8);
        }
#pragma unroll
        for (int t = 0; t < 4; t++) {
            int c = tid + t * 256;
            int row = c >> 4, ch = c & 15;
            cp_async_16(bBase + (row * LDB + ch * 8) * 2,
                        Bb + (size_t)(k0 + row) * N + ch * 8);
        }
        cp_commit();
    };

    float acc[4][4][4];
#pragma unroll
    for (int i = 0; i < 4; i++)
#pragma unroll
        for (int j = 0; j < 4; j++)
#pragma unroll
            for (int r = 0; r < 4; r++) acc[i][j][r] = 0.0f;

    const int KT = K / BK;
    issue(0, 0);
    issue(1, 1);

    // ldmatrix lane geometry (validated R4/R5)
    const int q = lane >> 3, r8 = lane & 7;
    const int aRow = r8 + (q & 1) * 8;
    const int aK8 = (q >> 1) * 8;
    const int bRow = r8 + (q & 1) * 8;
    const int bC8 = (q >> 1) * 8;

    for (int kt = 0; kt < KT; kt++) {
        cp_wait<STAGES - 2>();
        __syncthreads();   // also guards reuse of stage (kt-1)%3 prefetch target
        const int s = kt % STAGES;

        if (kt + 2 < KT) issue((kt + 2) % STAGES, kt + 2);
        else cp_commit();                        // uniform group accounting

        const uint32_t aSt = sAu + s * A_STAGE * 2;
        const uint32_t bSt = sBu + s * B_STAGE * 2;

        // B-fragment ping-pong: load B(kk+1) while MMAs consume B(kk)
        uint32_t rbb[2][4][2];
        auto loadB = [&](uint32_t (*rb)[2], int kk) {
#pragma unroll
            for (int p = 0; p < 2; p++) {
                uint32_t t4[4];
                ldsm_x4_t(t4, bSt + ((kk * 16 + bRow) * LDB + wn + p * 16 + bC8) * 2);
                rb[2 * p][0] = t4[0]; rb[2 * p][1] = t4[1];
                rb[2 * p + 1][0] = t4[2]; rb[2 * p + 1][1] = t4[3];
            }
        };
        loadB(rbb[0], 0);
#pragma unroll
        for (int kk = 0; kk < BK / 16; kk++) {
            uint32_t ra[4][4];
#pragma unroll
            for (int i = 0; i < 4; i++)
                ldsm_x4(ra[i], aSt + ((wm + i * 16 + aRow) * LDA + kk * 16 + aK8) * 2);
            if (kk < BK / 16 - 1) loadB(rbb[(kk + 1) & 1], kk + 1);
            uint32_t (*rb)[2] = rbb[kk & 1];
#pragma unroll
            for (int i = 0; i < 4; i++)
#pragma unroll
                for (int j = 0; j < 4; j++)
                    mma_16816(acc[i][j], ra[i], rb[j]);
        }
    }

    // epilogue: fused bias, direct stores
    const int gId = lane >> 2, tI = lane & 3;
#pragma unroll
    for (int i = 0; i < 4; i++) {
        const int row0 = bm * BM + wm + i * 16 + gId;
#pragma unroll
        for (int j = 0; j < 4; j++) {
            const int col = bn * BN + wn + j * 8 + tI * 2;
            const float bx = bias[col], by = bias[col + 1];
            float2 v0 = make_float2(acc[i][j][0] + bx, acc[i][j][1] + by);
            float2 v1 = make_float2(acc[i][j][2] + bx, acc[i][j][3] + by);
            *reinterpret_cast<float2*>(C + (size_t)row0 * N + col) = v0;
            *reinterpret_cast<float2*>(C + (size_t)(row0 + 8) * N + col) = v1;
        }
    }
}

// ---------------------------------------------------------------------------
// Launch
// ---------------------------------------------------------------------------
extern "C" void kernel_launch(void* const* d_in, const int* in_sizes, int n_in,
                              void* d_out, int out_size) {
    const float* x    = (const float*)d_in[0];   // [M, K]
    const float* w    = (const float*)d_in[1];   // [K, N]
    const float* bias = (const float*)d_in[2];   // [N]

    const int N = in_sizes[2];
    const int K = in_sizes[1] / N;
    const int M = in_sizes[0] / K;

    __half* gA = nullptr;
    __half* gB = nullptr;
    cudaGetSymbolAddress((void**)&gA, g_A);
    cudaGetSymbolAddress((void**)&gB, g_B);

    {   // quant+dequant x and W (both have contiguous 128-blocks)
        int quadsA = in_sizes[0] / 512;
        int quadsB = in_sizes[1] / 512;
        quant_kernel<<<(quadsA + 7) / 8, 256>>>(x, gA, quadsA);
        quant_kernel<<<(quadsB + 7) / 8, 256>>>(w, gB, quadsB);
    }
    {   // GEMM + fused bias
        static bool attr_set = false;
        if (!attr_set) {
            cudaFuncSetAttribute(gemm_mma_kernel,
                                 cudaFuncAttributeMaxDynamicSharedMemorySize,
                                 (int)SMEM_BYTES);
            attr_set = true;
        }
        dim3 grid(N / BN, M / BM);   // (32, 128) -> panel swizzle inside
        gemm_mma_kernel<<<grid, 256, SMEM_BYTES>>>(gA, gB, bias, (float*)d_out,
                                                   M, N, K);
    }
}